// round 13
// baseline (speedup 1.0000x reference)
#include <cuda_runtime.h>
#include <cuda_fp16.h>

#define NBINS   513
#define NB      64
#define NFRAMES 512
#define OUT_PER_B 130816           // 511*256
#define TOTAL_FRAMES (NB * NFRAMES)

// ---------------- compile-time tables ----------------
struct alignas(16) Tabs {
    float2 tw[512];    // cis(+2*pi*r/512)
    float2 ztw[512];   // cis(+2*pi*k/1024)
    float  win[1024];  // hann(n) / (1.5 * 512)
};

constexpr double KPI = 3.141592653589793238462643383279502884;

constexpr double ksin(double x) {          // |x| <= pi, Taylor
    double x2 = x * x, t = x, s = x;
    for (int i = 1; i <= 13; ++i) { t *= -x2 / double((2 * i) * (2 * i + 1)); s += t; }
    return s;
}
constexpr double kcos(double x) {          // |x| <= pi
    double y = KPI * 0.5 - x;              // in [-pi/2, 3pi/2]
    if (y > KPI) y -= 2.0 * KPI;
    return ksin(y);
}
constexpr float2 kcis(double a) {          // a in [0, 2pi)
    if (a > KPI) a -= 2.0 * KPI;
    return { (float)kcos(a), (float)ksin(a) };
}
constexpr Tabs mk_tabs() {
    Tabs T{};
    for (int r = 0; r < 512; ++r) {
        T.tw[r]  = kcis(2.0 * KPI * r / 512.0);
        T.ztw[r] = kcis(2.0 * KPI * r / 1024.0);
    }
    for (int n = 0; n < 1024; ++n) {
        double a = 2.0 * KPI * n / 1024.0;
        if (a > KPI) a -= 2.0 * KPI;
        T.win[n] = (float)((0.5 - 0.5 * kcos(a)) / 768.0);
    }
    return T;
}
__device__ const Tabs TAB = mk_tabs();

// fp16 scratch frames: uint holds half2 = samples (2m, 2m+1).
__device__ uint4 g_h4[(size_t)TOTAL_FRAMES * 128];

__device__ __forceinline__ float2 cmul(float2 a, float2 b) {
    return make_float2(a.x * b.x - a.y * b.y, a.x * b.y + a.y * b.x);
}
// inverse DFT4: y_n = sum_r x_r * i^(n*r)
__device__ __forceinline__ void idft4(float2 a, float2 b, float2 c, float2 d,
                                      float2& y0, float2& y1, float2& y2, float2& y3) {
    float2 s0 = make_float2(a.x + c.x, a.y + c.y);
    float2 d0 = make_float2(a.x - c.x, a.y - c.y);
    float2 s1 = make_float2(b.x + d.x, b.y + d.y);
    float2 d1 = make_float2(b.x - d.x, b.y - d.y);
    y0 = make_float2(s0.x + s1.x, s0.y + s1.y);
    y1 = make_float2(d0.x - d1.y, d0.y + d1.x);   // d0 + i*d1
    y2 = make_float2(s0.x - s1.x, s0.y - s1.y);
    y3 = make_float2(d0.x + d1.y, d0.y - d1.x);   // d0 - i*d1
}

__global__ __launch_bounds__(128) void istft_pass1(
    const float* __restrict__ re, const float* __restrict__ im, int block_base) {
    const int lane  = threadIdx.x & 31;
    const int frame = (block_base + blockIdx.x) * 4 + (threadIdx.x >> 5);
    const float* rp = re + (size_t)frame * NBINS;
    const float* ip = im + (size_t)frame * NBINS;

    // ---- Load + rfft->complex pack: Z[k2] for k = lane + 32*k2 ----
    float2 z[16];
    #pragma unroll
    for (int k2 = 0; k2 < 16; ++k2) {
        const int k = lane + 32 * k2;
        float xar = __ldg(rp + k),       xai = __ldg(ip + k);
        float xbr = __ldg(rp + 512 - k), xbi = __ldg(ip + 512 - k);
        if (k == 0) { xai = 0.0f; xbi = 0.0f; }   // c2r drops imag(DC), imag(Nyquist)
        float2 wz = TAB.ztw[k];                   // coalesced
        float Ex = 0.5f * (xar + xbr), Ey = 0.5f * (xai - xbi);
        float Dx = 0.5f * (xar - xbr), Dy = 0.5f * (xai + xbi);
        float Ox = wz.x * Dx - wz.y * Dy;
        float Oy = wz.x * Dy + wz.y * Dx;
        z[k2] = make_float2(Ex - Oy, Ey + Ox);
    }

    // ---- 16-pt inverse DFT over k2 in registers (constant twiddles) ----
    float2 G[16];   // G[k2a*4 + n2b]
    #pragma unroll
    for (int g = 0; g < 4; ++g)
        idft4(z[g], z[g + 4], z[g + 8], z[g + 12],
              G[g * 4 + 0], G[g * 4 + 1], G[g * 4 + 2], G[g * 4 + 3]);

    {   // G[g][n] *= cis(2*pi*g*n/16) -- immediates
        const float2 w1 = { 0.92387953251f,  0.38268343236f };
        const float2 w2 = { 0.70710678119f,  0.70710678119f };
        const float2 w3 = { 0.38268343236f,  0.92387953251f };
        const float2 w6 = {-0.70710678119f,  0.70710678119f };
        const float2 w9 = {-0.92387953251f, -0.38268343236f };
        G[5]  = cmul(G[5],  w1);
        G[6]  = cmul(G[6],  w2);
        G[7]  = cmul(G[7],  w3);
        G[9]  = cmul(G[9],  w2);
        G[10] = make_float2(-G[10].y, G[10].x);
        G[11] = cmul(G[11], w6);
        G[13] = cmul(G[13], w3);
        G[14] = cmul(G[14], w6);
        G[15] = cmul(G[15], w9);
    }

    float2 B[16];   // B[n2]
    #pragma unroll
    for (int n2b = 0; n2b < 4; ++n2b)
        idft4(G[0 * 4 + n2b], G[1 * 4 + n2b], G[2 * 4 + n2b], G[3 * 4 + n2b],
              B[n2b + 0], B[n2b + 4], B[n2b + 8], B[n2b + 12]);

    // ---- per-lane twiddle: B[n2] *= t1^n2, t1 = cis(2*pi*lane/512) ----
    // Single COALESCED load + cmul recurrence (no strided table walks).
    const float2 t1 = TAB.tw[lane];
    float2 tc = t1;
    B[1] = cmul(B[1], t1);
    #pragma unroll
    for (int n2 = 2; n2 < 16; ++n2) {
        tc = cmul(tc, t1);
        B[n2] = cmul(B[n2], tc);
    }

    // Stage twiddle bases via squarings: A_m = cis(pi*lane/m) = t1^(256/m).
    const float2 t16  = cmul(tc, t1);     // t1^16 = cis(pi*lane/16)
    const float2 t32  = cmul(t16, t16);   // cis(pi*lane/8)
    const float2 t64  = cmul(t32, t32);   // cis(pi*lane/4)
    const float2 t128 = cmul(t64, t64);   // cis(pi*lane/2)

    // ---- 32-pt inverse DFT across lanes: 5 DIF shuffle stages ----
    // Reference butterfly (validated R6): out_low = self+exch,
    //   out_up = w*(exch-self), w = cis(pi*(lane&(m-1))/m).
    // On up lanes A_m = -w, so equivalently:
    //   d = self + s*exch  (s = up ? -1 : +1)
    //   out = d * w_eff,   w_eff = up ? A_m : (1,0)   [hoisted SELs]
    #pragma unroll
    for (int st = 0; st < 4; ++st) {
        const int m = 16 >> st;
        const bool up = (lane & m) != 0;
        const float s = up ? -1.0f : 1.0f;
        const float2 A = (st == 0) ? t16 : (st == 1) ? t32 : (st == 2) ? t64 : t128;
        const float wx = up ? A.x : 1.0f;
        const float wy = up ? A.y : 0.0f;
        #pragma unroll
        for (int n2 = 0; n2 < 16; ++n2) {
            float ex = __shfl_xor_sync(0xffffffffu, B[n2].x, m);
            float ey = __shfl_xor_sync(0xffffffffu, B[n2].y, m);
            float dx = fmaf(s, ex, B[n2].x);
            float dy = fmaf(s, ey, B[n2].y);
            B[n2] = make_float2(wx * dx - wy * dy, wx * dy + wy * dx);
        }
    }
    {   // last stage m=1: w == 1 for all lanes; out = exch + s*self
        const float s = (lane & 1) ? -1.0f : 1.0f;
        #pragma unroll
        for (int n2 = 0; n2 < 16; ++n2) {
            float ex = __shfl_xor_sync(0xffffffffu, B[n2].x, 1);
            float ey = __shfl_xor_sync(0xffffffffu, B[n2].y, 1);
            B[n2] = make_float2(fmaf(s, B[n2].x, ex), fmaf(s, B[n2].y, ey));
        }
    }

    // Lane L holds y[n2 + 16*R], R = bitrev5(L): samples [32R, 32R+32).
    const int R = (int)(__brev((unsigned)lane) >> 27);
    const float4* w4p = (const float4*)TAB.win + 8 * R;
    unsigned us[16];
    #pragma unroll
    for (int j = 0; j < 8; ++j) {
        float4 wv = w4p[j];
        float2 y0 = B[2 * j], y1 = B[2 * j + 1];
        __half2 h0 = __floats2half2_rn(y0.x * wv.x, y0.y * wv.y);
        __half2 h1 = __floats2half2_rn(y1.x * wv.z, y1.y * wv.w);
        us[2 * j]     = *reinterpret_cast<unsigned*>(&h0);
        us[2 * j + 1] = *reinterpret_cast<unsigned*>(&h1);
    }
    uint4* dst = (uint4*)((unsigned*)g_h4 + (size_t)frame * 512 + 16 * R);
    dst[0] = make_uint4(us[0],  us[1],  us[2],  us[3]);
    dst[1] = make_uint4(us[4],  us[5],  us[6],  us[7]);
    dst[2] = make_uint4(us[8],  us[9],  us[10], us[11]);
    dst[3] = make_uint4(us[12], us[13], us[14], us[15]);
}

__global__ __launch_bounds__(256) void istft_pass2(float* __restrict__ out) {
    const int idx = blockIdx.x * 256 + threadIdx.x;
    const int p4 = idx * 4;
    if (p4 >= OUT_PER_B) return;
    const int b = blockIdx.y;
    const int pg = p4 + 512;
    const int fh = pg >> 8;
    const uint2* base = (const uint2*)g_h4 + (size_t)b * NFRAMES * 256;

    float4 acc = make_float4(0.f, 0.f, 0.f, 0.f);
    #pragma unroll
    for (int j = 0; j < 4; ++j) {
        int f = fh - j;
        if (f >= 0 && f < NFRAMES) {
            uint2 q = base[f * 256 + ((pg - (f << 8)) >> 2)];
            __half2 a = *reinterpret_cast<__half2*>(&q.x);
            __half2 c = *reinterpret_cast<__half2*>(&q.y);
            float2 fa = __half22float2(a);
            float2 fc = __half22float2(c);
            acc.x += fa.x; acc.y += fa.y; acc.z += fc.x; acc.w += fc.y;
        }
    }
    *(float4*)(out + (size_t)b * OUT_PER_B + p4) = acc;
}

extern "C" void kernel_launch(void* const* d_in, const int* in_sizes, int n_in,
                              void* d_out, int out_size) {
    const float* re = (const float*)d_in[0];
    const float* im = (const float*)d_in[1];
    // 3-way split of pass1 -> 4 launches per replay, so ncu's "-s 5 -c 1"
    // (6th launch) captures a pass1 chunk instead of always pass2.
    const int total_blocks = TOTAL_FRAMES / 4;   // 8192
    const int c0 = 2731, c1 = 2731, c2 = total_blocks - c0 - c1;
    istft_pass1<<<c0, 128>>>(re, im, 0);
    istft_pass1<<<c1, 128>>>(re, im, c0);
    istft_pass1<<<c2, 128>>>(re, im, c0 + c1);
    dim3 g2((OUT_PER_B / 4 + 255) / 256, NB);
    istft_pass2<<<g2, 256>>>((float*)d_out);
}

// round 15
// speedup vs baseline: 1.0532x; 1.0532x over previous
#include <cuda_runtime.h>
#include <cuda_fp16.h>

#define NBINS   513
#define NB      64
#define NFRAMES 512
#define OUT_PER_B 130816           // 511*256
#define TOTAL_FRAMES (NB * NFRAMES)

// ---------------- compile-time tables ----------------
struct alignas(16) Tabs {
    float2 tw[512];    // cis(+2*pi*r/512)
    float2 ztw[512];   // cis(+2*pi*k/1024)
    float  win[1024];  // hann(n) / (1.5 * 512)
};

constexpr double KPI = 3.141592653589793238462643383279502884;

constexpr double ksin(double x) {          // |x| <= pi, Taylor
    double x2 = x * x, t = x, s = x;
    for (int i = 1; i <= 13; ++i) { t *= -x2 / double((2 * i) * (2 * i + 1)); s += t; }
    return s;
}
constexpr double kcos(double x) {          // |x| <= pi
    double y = KPI * 0.5 - x;              // in [-pi/2, 3pi/2]
    if (y > KPI) y -= 2.0 * KPI;
    return ksin(y);
}
constexpr float2 kcis(double a) {          // a in [0, 2pi)
    if (a > KPI) a -= 2.0 * KPI;
    return { (float)kcos(a), (float)ksin(a) };
}
constexpr Tabs mk_tabs() {
    Tabs T{};
    for (int r = 0; r < 512; ++r) {
        T.tw[r]  = kcis(2.0 * KPI * r / 512.0);
        T.ztw[r] = kcis(2.0 * KPI * r / 1024.0);
    }
    for (int n = 0; n < 1024; ++n) {
        double a = 2.0 * KPI * n / 1024.0;
        if (a > KPI) a -= 2.0 * KPI;
        T.win[n] = (float)((0.5 - 0.5 * kcos(a)) / 768.0);
    }
    return T;
}
__device__ const Tabs TAB = mk_tabs();

// fp16 scratch frames: frame = 128 uint4 (1024 fp16 samples).
__device__ uint4 g_h4[(size_t)TOTAL_FRAMES * 128];

__device__ __forceinline__ float2 cmul(float2 a, float2 b) {
    return make_float2(a.x * b.x - a.y * b.y, a.x * b.y + a.y * b.x);
}
__device__ __forceinline__ float2 cadd(float2 a, float2 b) {
    return make_float2(a.x + b.x, a.y + b.y);
}
__device__ __forceinline__ float2 csub(float2 a, float2 b) {
    return make_float2(a.x - b.x, a.y - b.y);
}
// inverse DFT4: y_n = sum_r x_r * i^(n*r)
__device__ __forceinline__ void idft4(float2 a, float2 b, float2 c, float2 d,
                                      float2& y0, float2& y1, float2& y2, float2& y3) {
    float2 s0 = cadd(a, c), d0 = csub(a, c);
    float2 s1 = cadd(b, d), d1 = csub(b, d);
    y0 = cadd(s0, s1);
    y1 = make_float2(d0.x - d1.y, d0.y + d1.x);   // d0 + i*d1
    y2 = csub(s0, s1);
    y3 = make_float2(d0.x + d1.y, d0.y - d1.x);   // d0 - i*d1
}

// 64 threads per frame, 8 complex elements per thread. 4 frames per 256-thr CTA.
__global__ __launch_bounds__(256) void istft_pass1(
    const float* __restrict__ re, const float* __restrict__ im) {
    __shared__ float2 sEx[8][256];   // [elem][thread] -- conflict-free exchange

    const int t    = threadIdx.x;
    const int tid  = t & 63;         // thread-in-frame
    const int frame = blockIdx.x * 4 + (t >> 6);
    const float* rp = re + (size_t)frame * NBINS;
    const float* ip = im + (size_t)frame * NBINS;

    // ---- Load + rfft->complex pack: Z[k2] for k = tid + 64*k2 ----
    float2 z[8];
    #pragma unroll
    for (int k2 = 0; k2 < 8; ++k2) {
        const int k = tid + 64 * k2;
        float xar = __ldg(rp + k),       xai = __ldg(ip + k);
        float xbr = __ldg(rp + 512 - k), xbi = __ldg(ip + 512 - k);
        if (k == 0) { xai = 0.0f; xbi = 0.0f; }   // c2r drops imag(DC), imag(Nyquist)
        float2 wz = TAB.ztw[k];                   // coalesced
        float Ex = 0.5f * (xar + xbr), Ey = 0.5f * (xai - xbi);
        float Dx = 0.5f * (xar - xbr), Dy = 0.5f * (xai + xbi);
        float Ox = wz.x * Dx - wz.y * Dy;
        float Oy = wz.x * Dy + wz.y * Dx;
        z[k2] = make_float2(Ex - Oy, Ey + Ox);
    }

    // ---- 8-pt natural inverse DFT over k2 (constant twiddles) ----
    float2 B[8];
    {
        float2 E0, E1, E2, E3, O0, O1, O2, O3;
        idft4(z[0], z[2], z[4], z[6], E0, E1, E2, E3);
        idft4(z[1], z[3], z[5], z[7], O0, O1, O2, O3);
        const float C = 0.70710678118654752f;
        float2 w1o = make_float2(C * (O1.x - O1.y), C * (O1.x + O1.y));  // cis(pi/4)*O1
        float2 w2o = make_float2(-O2.y, O2.x);                           // i*O2
        float2 w3o = make_float2(-C * (O3.x + O3.y), C * (O3.x - O3.y)); // cis(3pi/4)*O3
        B[0] = cadd(E0, O0);  B[4] = csub(E0, O0);
        B[1] = cadd(E1, w1o); B[5] = csub(E1, w1o);
        B[2] = cadd(E2, w2o); B[6] = csub(E2, w2o);
        B[3] = cadd(E3, w3o); B[7] = csub(E3, w3o);
    }

    // ---- per-thread twiddle: B[n2] *= t1^n2, t1 = cis(2*pi*tid/512) ----
    const float2 t1 = TAB.tw[tid];
    float2 tc = t1;
    B[1] = cmul(B[1], t1);
    #pragma unroll
    for (int n2 = 2; n2 < 8; ++n2) {
        tc = cmul(tc, t1);
        B[n2] = cmul(B[n2], tc);
    }
    // Stage bases A_m = cis(pi*tid/m) = t1^(256/m); tc == t1^7 here.
    const float2 t8   = cmul(tc, t1);     // A_32
    const float2 t16  = cmul(t8, t8);     // A_16
    const float2 t32  = cmul(t16, t16);   // A_8
    const float2 t64  = cmul(t32, t32);   // A_4
    const float2 t128 = cmul(t64, t64);   // A_2

    // ---- 64-pt inverse DFT across threads: 6 DIF stages ----
    // Butterfly: d = self + s*exch (s=-1 on up side), out = d * w_eff,
    // w_eff = up ? A_m : (1,0). (Identical algebra to validated R6 stages.)

    // Stage m=32: cross-warp -> one smem exchange.
    {
        #pragma unroll
        for (int j = 0; j < 8; ++j) sEx[j][t] = B[j];
        __syncthreads();
        const bool up = (tid & 32) != 0;
        const float s = up ? -1.0f : 1.0f;
        const float wx = up ? t8.x : 1.0f;
        const float wy = up ? t8.y : 0.0f;
        #pragma unroll
        for (int j = 0; j < 8; ++j) {
            float2 q = sEx[j][t ^ 32];
            float dx = fmaf(s, q.x, B[j].x);
            float dy = fmaf(s, q.y, B[j].y);
            B[j] = make_float2(wx * dx - wy * dy, wx * dy + wy * dx);
        }
    }

    // Stages m=16,8,4,2: intra-warp shuffles.
    #pragma unroll
    for (int st = 0; st < 4; ++st) {
        const int m = 16 >> st;
        const bool up = (tid & m) != 0;
        const float s = up ? -1.0f : 1.0f;
        const float2 A = (st == 0) ? t16 : (st == 1) ? t32 : (st == 2) ? t64 : t128;
        const float wx = up ? A.x : 1.0f;
        const float wy = up ? A.y : 0.0f;
        #pragma unroll
        for (int j = 0; j < 8; ++j) {
            float ex = __shfl_xor_sync(0xffffffffu, B[j].x, m);
            float ey = __shfl_xor_sync(0xffffffffu, B[j].y, m);
            float dx = fmaf(s, ex, B[j].x);
            float dy = fmaf(s, ey, B[j].y);
            B[j] = make_float2(wx * dx - wy * dy, wx * dy + wy * dx);
        }
    }
    {   // last stage m=1: w == 1; out = exch + s*self
        const float s = (tid & 1) ? -1.0f : 1.0f;
        #pragma unroll
        for (int j = 0; j < 8; ++j) {
            float ex = __shfl_xor_sync(0xffffffffu, B[j].x, 1);
            float ey = __shfl_xor_sync(0xffffffffu, B[j].y, 1);
            B[j] = make_float2(fmaf(s, B[j].x, ex), fmaf(s, B[j].y, ey));
        }
    }

    // Thread holds y[n2 + 8*R], R = bitrev6(tid): samples x[16R .. 16R+16).
    const int R = (int)(__brev((unsigned)tid) >> 26);
    const float4* w4p = (const float4*)TAB.win + 4 * R;
    unsigned us[8];
    #pragma unroll
    for (int j = 0; j < 4; ++j) {
        float4 wv = w4p[j];
        float2 y0 = B[2 * j], y1 = B[2 * j + 1];
        __half2 h0 = __floats2half2_rn(y0.x * wv.x, y0.y * wv.y);
        __half2 h1 = __floats2half2_rn(y1.x * wv.z, y1.y * wv.w);
        us[2 * j]     = *reinterpret_cast<unsigned*>(&h0);
        us[2 * j + 1] = *reinterpret_cast<unsigned*>(&h1);
    }
    uint4* dst = g_h4 + (size_t)frame * 128 + 2 * R;
    dst[0] = make_uint4(us[0], us[1], us[2], us[3]);
    dst[1] = make_uint4(us[4], us[5], us[6], us[7]);
}

__global__ __launch_bounds__(256) void istft_pass2(float* __restrict__ out) {
    const int idx = blockIdx.x * 256 + threadIdx.x;
    const int p4 = idx * 4;
    if (p4 >= OUT_PER_B) return;
    const int b = blockIdx.y;
    const int pg = p4 + 512;
    const int fh = pg >> 8;
    const uint2* base = (const uint2*)g_h4 + (size_t)b * NFRAMES * 256;

    float4 acc = make_float4(0.f, 0.f, 0.f, 0.f);
    #pragma unroll
    for (int j = 0; j < 4; ++j) {
        int f = fh - j;
        if (f >= 0 && f < NFRAMES) {
            uint2 q = base[f * 256 + ((pg - (f << 8)) >> 2)];
            __half2 a = *reinterpret_cast<__half2*>(&q.x);
            __half2 c = *reinterpret_cast<__half2*>(&q.y);
            float2 fa = __half22float2(a);
            float2 fc = __half22float2(c);
            acc.x += fa.x; acc.y += fa.y; acc.z += fc.x; acc.w += fc.y;
        }
    }
    *(float4*)(out + (size_t)b * OUT_PER_B + p4) = acc;
}

extern "C" void kernel_launch(void* const* d_in, const int* in_sizes, int n_in,
                              void* d_out, int out_size) {
    const float* re = (const float*)d_in[0];
    const float* im = (const float*)d_in[1];
    istft_pass1<<<TOTAL_FRAMES / 4, 256>>>(re, im);
    dim3 g2((OUT_PER_B / 4 + 255) / 256, NB);
    istft_pass2<<<g2, 256>>>((float*)d_out);
}

// round 17
// speedup vs baseline: 1.0934x; 1.0382x over previous
#include <cuda_runtime.h>
#include <cuda_fp16.h>

#define NBINS   513
#define NB      64
#define NFRAMES 512
#define OUT_PER_B 130816           // 511*256
#define TOTAL_FRAMES (NB * NFRAMES)

typedef unsigned long long ull;

// ---------------- compile-time tables ----------------
struct alignas(16) Tabs {
    float2 tw[512];    // cis(+2*pi*r/512)
    float2 ztw[512];   // cis(+2*pi*k/1024)
    float  win[1024];  // hann(n) / (1.5 * 1024)  [extra /2 absorbs dropped 0.5s]
};

constexpr double KPI = 3.141592653589793238462643383279502884;

constexpr double ksin(double x) {          // |x| <= pi, Taylor
    double x2 = x * x, t = x, s = x;
    for (int i = 1; i <= 13; ++i) { t *= -x2 / double((2 * i) * (2 * i + 1)); s += t; }
    return s;
}
constexpr double kcos(double x) {          // |x| <= pi
    double y = KPI * 0.5 - x;              // in [-pi/2, 3pi/2]
    if (y > KPI) y -= 2.0 * KPI;
    return ksin(y);
}
constexpr float2 kcis(double a) {          // a in [0, 2pi)
    if (a > KPI) a -= 2.0 * KPI;
    return { (float)kcos(a), (float)ksin(a) };
}
constexpr Tabs mk_tabs() {
    Tabs T{};
    for (int r = 0; r < 512; ++r) {
        T.tw[r]  = kcis(2.0 * KPI * r / 512.0);
        T.ztw[r] = kcis(2.0 * KPI * r / 1024.0);
    }
    for (int n = 0; n < 1024; ++n) {
        double a = 2.0 * KPI * n / 1024.0;
        if (a > KPI) a -= 2.0 * KPI;
        T.win[n] = (float)((0.5 - 0.5 * kcos(a)) / 1536.0);  // /768 * 0.5
    }
    return T;
}
__device__ const Tabs TAB = mk_tabs();

// fp16 scratch frames: frame = 128 uint4 (1024 fp16 samples).
__device__ uint4 g_h4[(size_t)TOTAL_FRAMES * 128];

// ---------------- f32x2 packed helpers ----------------
__device__ __forceinline__ ull pk(float x, float y) {
    ull r; asm("mov.b64 %0,{%1,%2};" : "=l"(r) : "f"(x), "f"(y)); return r;
}
__device__ __forceinline__ void upk(ull v, float& x, float& y) {
    asm("mov.b64 {%0,%1},%2;" : "=f"(x), "=f"(y) : "l"(v));
}
__device__ __forceinline__ ull f2add(ull a, ull b) {
    ull d; asm("add.rn.f32x2 %0,%1,%2;" : "=l"(d) : "l"(a), "l"(b)); return d;
}
__device__ __forceinline__ ull f2mul(ull a, ull b) {
    ull d; asm("mul.rn.f32x2 %0,%1,%2;" : "=l"(d) : "l"(a), "l"(b)); return d;
}
__device__ __forceinline__ ull f2fma(ull a, ull b, ull c) {
    ull d; asm("fma.rn.f32x2 %0,%1,%2,%3;" : "=l"(d) : "l"(a), "l"(b), "l"(c)); return d;
}

__device__ __forceinline__ float2 cmul(float2 a, float2 b) {
    return make_float2(a.x * b.x - a.y * b.y, a.x * b.y + a.y * b.x);
}

// 64 threads per frame, 8 complex elements per thread (as SoA f32x2 carriers).
__global__ __launch_bounds__(256) void istft_pass1(
    const float* __restrict__ re, const float* __restrict__ im) {
    __shared__ ull sEx[8][256];   // packed exchange for the m=32 stage (16 KB)

    const int t    = threadIdx.x;
    const int tid  = t & 63;
    const int frame = blockIdx.x * 4 + (t >> 6);
    const float* rp = re + (size_t)frame * NBINS;
    const float* ip = im + (size_t)frame * NBINS;

    const ull NEG1 = pk(-1.0f, -1.0f);

    // ---- Load + rfft->complex pack (0.5 factors folded into window table) ----
    // z[k2] = 2*Z[k], k = tid + 64*k2.
    float2 z[8];
    #pragma unroll
    for (int k2 = 0; k2 < 8; ++k2) {
        const int k = tid + 64 * k2;
        float xar = __ldg(rp + k),       xai = __ldg(ip + k);
        float xbr = __ldg(rp + 512 - k), xbi = __ldg(ip + 512 - k);
        if (k == 0) { xai = 0.0f; xbi = 0.0f; }   // c2r drops imag(DC), imag(Nyquist)
        float2 wz = TAB.ztw[k];
        float Ex = xar + xbr, Ey = xai - xbi;
        float Dx = xar - xbr, Dy = xai + xbi;
        float Ox = wz.x * Dx - wz.y * Dy;
        float Oy = wz.x * Dy + wz.y * Dx;
        z[k2] = make_float2(Ex - Oy, Ey + Ox);
    }

    // ---- Pack SoA carriers: X[p]=(z[2p].x, z[2p+1].x), Y[p] = imag parts ----
    ull X[4], Y[4];
    #pragma unroll
    for (int p = 0; p < 4; ++p) {
        X[p] = pk(z[2 * p].x, z[2 * p + 1].x);
        Y[p] = pk(z[2 * p].y, z[2 * p + 1].y);
    }

    // ---- packed 8-pt inverse DFT: even arm = lo lanes, odd arm = hi lanes ----
    {
        ull Xs0 = f2add(X[0], X[2]), Ys0 = f2add(Y[0], Y[2]);
        ull Xd0 = f2fma(X[2], NEG1, X[0]), Yd0 = f2fma(Y[2], NEG1, Y[0]);
        ull Xs1 = f2add(X[1], X[3]), Ys1 = f2add(Y[1], Y[3]);
        ull Xd1 = f2fma(X[3], NEG1, X[1]), Yd1 = f2fma(Y[3], NEG1, Y[1]);
        // R0 = s0+s1; R1 = d0 + i*d1; R2 = s0-s1; R3 = d0 - i*d1
        ull XR0 = f2add(Xs0, Xs1),        YR0 = f2add(Ys0, Ys1);
        ull XR1 = f2fma(Yd1, NEG1, Xd0),  YR1 = f2add(Yd0, Xd1);
        ull XR2 = f2fma(Xs1, NEG1, Xs0),  YR2 = f2fma(Ys1, NEG1, Ys0);
        ull XR3 = f2add(Xd0, Yd1),        YR3 = f2fma(Xd1, NEG1, Yd0);

        // unpack (E_k | O_k), combine with w = {1, cis(pi/4), i, cis(3pi/4)}
        float E0x,O0x,E0y,O0y, E1x,O1x,E1y,O1y, E2x,O2x,E2y,O2y, E3x,O3x,E3y,O3y;
        upk(XR0,E0x,O0x); upk(YR0,E0y,O0y);
        upk(XR1,E1x,O1x); upk(YR1,E1y,O1y);
        upk(XR2,E2x,O2x); upk(YR2,E2y,O2y);
        upk(XR3,E3x,O3x); upk(YR3,E3y,O3y);
        const float C = 0.70710678118654752f;
        float w1x = C * (O1x - O1y), w1y = C * (O1x + O1y);
        float w2x = -O2y,            w2y = O2x;
        float w3x = -C * (O3x + O3y), w3y = C * (O3x - O3y);
        float2 B[8];
        B[0] = make_float2(E0x + O0x, E0y + O0y);
        B[4] = make_float2(E0x - O0x, E0y - O0y);
        B[1] = make_float2(E1x + w1x, E1y + w1y);
        B[5] = make_float2(E1x - w1x, E1y - w1y);
        B[2] = make_float2(E2x + w2x, E2y + w2y);
        B[6] = make_float2(E2x - w2x, E2y - w2y);
        B[3] = make_float2(E3x + w3x, E3y + w3y);
        B[7] = make_float2(E3x - w3x, E3y - w3y);
        #pragma unroll
        for (int p = 0; p < 4; ++p) {
            X[p] = pk(B[2 * p].x, B[2 * p + 1].x);
            Y[p] = pk(B[2 * p].y, B[2 * p + 1].y);
        }
    }

    // ---- per-thread twiddles t1^n2 (scalar recurrence, packed apply) ----
    const float2 t1 = TAB.tw[tid];
    const float2 t2 = cmul(t1, t1);
    const float2 t3 = cmul(t2, t1);
    const float2 t4 = cmul(t2, t2);
    const float2 t5 = cmul(t4, t1);
    const float2 t6 = cmul(t4, t2);
    const float2 t7 = cmul(t4, t3);
    {
        ull Wx[4] = { pk(1.f, t1.x), pk(t2.x, t3.x), pk(t4.x, t5.x), pk(t6.x, t7.x) };
        ull Wy[4] = { pk(0.f, t1.y), pk(t2.y, t3.y), pk(t4.y, t5.y), pk(t6.y, t7.y) };
        ull WyN[4] = { pk(-0.f, -t1.y), pk(-t2.y, -t3.y), pk(-t4.y, -t5.y), pk(-t6.y, -t7.y) };
        #pragma unroll
        for (int p = 0; p < 4; ++p) {
            ull nX = f2fma(X[p], Wx[p], f2mul(Y[p], WyN[p]));
            ull nY = f2fma(Y[p], Wx[p], f2mul(X[p], Wy[p]));
            X[p] = nX; Y[p] = nY;
        }
    }

    // Stage bases A_m = cis(pi*tid/m) = t1^(256/m), via squarings.
    const float2 P8   = cmul(t4, t4);      // A_32
    const float2 P16  = cmul(P8, P8);      // A_16
    const float2 P32  = cmul(P16, P16);    // A_8
    const float2 P64  = cmul(P32, P32);    // A_4
    const float2 P128 = cmul(P64, P64);    // A_2

    // ---- stage m=32 (cross-warp, smem exchange) ----
    {
        #pragma unroll
        for (int j = 0; j < 4; ++j) { sEx[j][t] = X[j]; sEx[j + 4][t] = Y[j]; }
        __syncthreads();
        const bool up = (tid & 32) != 0;
        const float s = up ? -1.0f : 1.0f;
        const float wx = up ? P8.x : 1.0f;
        const float wy = up ? P8.y : 0.0f;
        const ull sP = pk(s, s), wxP = pk(wx, wx), wyP = pk(wy, wy), wyN = pk(-wy, -wy);
        #pragma unroll
        for (int j = 0; j < 4; ++j) {
            ull eX = sEx[j][t ^ 32], eY = sEx[j + 4][t ^ 32];
            ull dX = f2fma(eX, sP, X[j]);
            ull dY = f2fma(eY, sP, Y[j]);
            X[j] = f2fma(dX, wxP, f2mul(dY, wyN));
            Y[j] = f2fma(dY, wxP, f2mul(dX, wyP));
        }
    }

    // ---- stages m=16,8,4,2 (intra-warp shuffles, 64-bit) ----
    #pragma unroll
    for (int st = 0; st < 4; ++st) {
        const int m = 16 >> st;
        const bool up = (tid & m) != 0;
        const float s = up ? -1.0f : 1.0f;
        const float2 A = (st == 0) ? P16 : (st == 1) ? P32 : (st == 2) ? P64 : P128;
        const float wx = up ? A.x : 1.0f;
        const float wy = up ? A.y : 0.0f;
        const ull sP = pk(s, s), wxP = pk(wx, wx), wyP = pk(wy, wy), wyN = pk(-wy, -wy);
        #pragma unroll
        for (int j = 0; j < 4; ++j) {
            ull eX = __shfl_xor_sync(0xffffffffu, X[j], m);
            ull eY = __shfl_xor_sync(0xffffffffu, Y[j], m);
            ull dX = f2fma(eX, sP, X[j]);
            ull dY = f2fma(eY, sP, Y[j]);
            X[j] = f2fma(dX, wxP, f2mul(dY, wyN));
            Y[j] = f2fma(dY, wxP, f2mul(dX, wyP));
        }
    }
    {   // last stage m=1 (w == 1): out = s*self + exch
        const float s = (tid & 1) ? -1.0f : 1.0f;
        const ull sP = pk(s, s);
        #pragma unroll
        for (int j = 0; j < 4; ++j) {
            ull eX = __shfl_xor_sync(0xffffffffu, X[j], 1);
            ull eY = __shfl_xor_sync(0xffffffffu, Y[j], 1);
            X[j] = f2fma(X[j], sP, eX);
            Y[j] = f2fma(Y[j], sP, eY);
        }
    }

    // Thread holds y[n2 + 8*R], R = bitrev6(tid): samples x[16R .. 16R+16).
    const int R = (int)(__brev((unsigned)tid) >> 26);
    const float4* w4p = (const float4*)TAB.win + 4 * R;
    unsigned us[8];
    #pragma unroll
    for (int j = 0; j < 4; ++j) {
        float4 wv = w4p[j];
        float x0, x1, y0v, y1v;
        upk(X[j], x0, x1);
        upk(Y[j], y0v, y1v);
        __half2 h0 = __floats2half2_rn(x0 * wv.x, y0v * wv.y);
        __half2 h1 = __floats2half2_rn(x1 * wv.z, y1v * wv.w);
        us[2 * j]     = *reinterpret_cast<unsigned*>(&h0);
        us[2 * j + 1] = *reinterpret_cast<unsigned*>(&h1);
    }
    uint4* dst = g_h4 + (size_t)frame * 128 + 2 * R;
    dst[0] = make_uint4(us[0], us[1], us[2], us[3]);
    dst[1] = make_uint4(us[4], us[5], us[6], us[7]);
}

__global__ __launch_bounds__(256) void istft_pass2(float* __restrict__ out) {
    const int idx = blockIdx.x * 256 + threadIdx.x;
    const int p4 = idx * 4;
    if (p4 >= OUT_PER_B) return;
    const int b = blockIdx.y;
    const int pg = p4 + 512;
    const int fh = pg >> 8;
    const uint2* base = (const uint2*)g_h4 + (size_t)b * NFRAMES * 256;

    float4 acc = make_float4(0.f, 0.f, 0.f, 0.f);
    #pragma unroll
    for (int j = 0; j < 4; ++j) {
        int f = fh - j;
        if (f >= 0 && f < NFRAMES) {
            uint2 q = base[f * 256 + ((pg - (f << 8)) >> 2)];
            __half2 a = *reinterpret_cast<__half2*>(&q.x);
            __half2 c = *reinterpret_cast<__half2*>(&q.y);
            float2 fa = __half22float2(a);
            float2 fc = __half22float2(c);
            acc.x += fa.x; acc.y += fa.y; acc.z += fc.x; acc.w += fc.y;
        }
    }
    *(float4*)(out + (size_t)b * OUT_PER_B + p4) = acc;
}

extern "C" void kernel_launch(void* const* d_in, const int* in_sizes, int n_in,
                              void* d_out, int out_size) {
    const float* re = (const float*)d_in[0];
    const float* im = (const float*)d_in[1];
    istft_pass1<<<TOTAL_FRAMES / 4, 256>>>(re, im);
    dim3 g2((OUT_PER_B / 4 + 255) / 256, NB);
    istft_pass2<<<g2, 256>>>((float*)d_out);
}